// round 14
// baseline (speedup 1.0000x reference)
#include <cuda_runtime.h>

#define BATCH 1024
#define TLEN  336
#define ISZ   64
#define HSZ   256
#define FH    1024      // 4*H
#define KTOT  320       // H + I
#define BM    64
#define BN    128
#define KT    16
#define NKT   (KTOT/KT) // 20
#define NTHREADS 256
#define ASTRIDE 136     // 2*64 duplicated + 8 pad
#define BH (BATCH*HSZ)

// Scratch in __device__ globals (no allocation allowed)
__device__ float g_Wcat[KTOT*FH];   // [k][n], n = 4*u + gate (i,f,g,o)
__device__ float g_bias[FH];        // b_ih + b_hh, reordered
__device__ float g_h[2][BH];        // double-buffered hidden state
__device__ float g_c[BH];           // cell state (tile-private per step)

typedef unsigned long long ull;

__device__ __forceinline__ void fma2(ull &d, ull a, ull b){
    // packed fp32x2 FMA (Blackwell dual fp32 lanes)
    asm("fma.rn.f32x2 %0, %1, %2, %0;" : "+l"(d) : "l"(a), "l"(b));
}
__device__ __forceinline__ float lo32(ull v){ return __uint_as_float((unsigned)v); }
__device__ __forceinline__ float hi32(ull v){ return __uint_as_float((unsigned)(v >> 32)); }

__device__ __forceinline__ float sigf(float x){ return 1.f / (1.f + __expf(-x)); }
// tanh(x) = 1 - 2/(1+exp(2x)); saturates cleanly at +/-1, no inf/inf NaN
__device__ __forceinline__ float tanh_(float x){ return 1.f - 2.f / (1.f + __expf(2.f * x)); }

// Build Wcat/bias, zero h0/c0. Runs once per kernel_launch (deterministic).
__global__ void prep_kernel(const float* __restrict__ W_ih, const float* __restrict__ W_hh,
                            const float* __restrict__ b_ih, const float* __restrict__ b_hh){
    int idx = blockIdx.x * blockDim.x + threadIdx.x;
    if (idx < KTOT * FH){
        int k = idx >> 10;          // 0..319
        int n = idx & (FH - 1);     // 0..1023
        int u = n >> 2, g = n & 3;  // gate order i,f,g,o
        g_Wcat[idx] = (k < HSZ) ? W_hh[(g * HSZ + u) * HSZ + k]
                                : W_ih[(g * HSZ + u) * ISZ + (k - HSZ)];
    }
    if (idx < FH){
        int u = idx >> 2, g = idx & 3;
        g_bias[idx] = b_ih[g * HSZ + u] + b_hh[g * HSZ + u];
    }
    if (idx < BH){
        g_c[idx]    = 0.f;
        g_h[0][idx] = 0.f;
    }
}

// One LSTM timestep: gates = [h | x_t] @ Wcat + bias, fused gate epilogue.
// Tile 64(M=batch) x 128(N=gate cols) per block; 256 threads, 4x8 micro-tile
// computed as 4x4 packed f32x2 accumulators.
__global__ void __launch_bounds__(NTHREADS, 1)
lstm_step_kernel(const float* __restrict__ x, int t, float* __restrict__ out){
    __shared__ float As2[2][KT][ASTRIDE];   // A duplicated: As2[k][2m]=As2[k][2m+1]=A[m][k]
    __shared__ float Bs [2][KT][BN];        // Bs[k][n]

    const float* __restrict__ hread  = g_h[t & 1];
    float*       __restrict__ hwrite = g_h[(t + 1) & 1];

    const int tid = threadIdx.x;
    const int bm0 = blockIdx.y * BM;
    const int bn0 = blockIdx.x * BN;
    const int ty  = tid >> 4,  tx  = tid & 15;    // 16x16 compute threads
    const int am  = tid >> 2,  akq = tid & 3;     // A loader: row, k-quad
    const int bn4 = (tid & 31) * 4, bkk = tid >> 5; // B loader

    ull acc[4][4];
    #pragma unroll
    for (int r = 0; r < 4; r++)
        #pragma unroll
        for (int c = 0; c < 4; c++) acc[r][c] = 0ULL;

    float4 av, bv0, bv1;
    // prefetch k-tile 0 (h source)
    av  = *(const float4*)&hread[(bm0 + am) * HSZ + akq * 4];
    bv0 = *(const float4*)&g_Wcat[(bkk    ) * FH + bn0 + bn4];
    bv1 = *(const float4*)&g_Wcat[(bkk + 8) * FH + bn0 + bn4];
    *(float2*)&As2[0][akq * 4 + 0][2 * am] = make_float2(av.x, av.x);
    *(float2*)&As2[0][akq * 4 + 1][2 * am] = make_float2(av.y, av.y);
    *(float2*)&As2[0][akq * 4 + 2][2 * am] = make_float2(av.z, av.z);
    *(float2*)&As2[0][akq * 4 + 3][2 * am] = make_float2(av.w, av.w);
    *(float4*)&Bs[0][bkk    ][bn4] = bv0;
    *(float4*)&Bs[0][bkk + 8][bn4] = bv1;
    __syncthreads();

    #pragma unroll 2
    for (int kt = 0; kt < NKT; kt++){
        const int cur = kt & 1;
        if (kt < NKT - 1){
            const int kn = kt + 1;
            if (kn < 16)   // h portion of K (k < 256)
                av = *(const float4*)&hread[(bm0 + am) * HSZ + kn * KT + akq * 4];
            else           // x portion of K (k >= 256)
                av = *(const float4*)&x[(size_t)(bm0 + am) * (TLEN * ISZ)
                                        + (size_t)t * ISZ + (kn - 16) * KT + akq * 4];
            bv0 = *(const float4*)&g_Wcat[(kn * KT + bkk    ) * FH + bn0 + bn4];
            bv1 = *(const float4*)&g_Wcat[(kn * KT + bkk + 8) * FH + bn0 + bn4];
        }
        const float* Ap = &As2[cur][0][0];
        const float* Bp = &Bs [cur][0][0];
        #pragma unroll
        for (int k = 0; k < KT; k++){
            ulonglong2 a01 = *(const ulonglong2*)(Ap + k * ASTRIDE + ty * 8);
            ulonglong2 a23 = *(const ulonglong2*)(Ap + k * ASTRIDE + ty * 8 + 4);
            ulonglong2 b01 = *(const ulonglong2*)(Bp + k * BN + tx * 8);
            ulonglong2 b23 = *(const ulonglong2*)(Bp + k * BN + tx * 8 + 4);
            ull ar[4] = {a01.x, a01.y, a23.x, a23.y};
            ull bc[4] = {b01.x, b01.y, b23.x, b23.y};
            #pragma unroll
            for (int r = 0; r < 4; r++)
                #pragma unroll
                for (int c = 0; c < 4; c++)
                    fma2(acc[r][c], ar[r], bc[c]);
        }
        if (kt < NKT - 1){
            const int nb = cur ^ 1;   // safe: nb was last read before previous sync
            *(float2*)&As2[nb][akq * 4 + 0][2 * am] = make_float2(av.x, av.x);
            *(float2*)&As2[nb][akq * 4 + 1][2 * am] = make_float2(av.y, av.y);
            *(float2*)&As2[nb][akq * 4 + 2][2 * am] = make_float2(av.z, av.z);
            *(float2*)&As2[nb][akq * 4 + 3][2 * am] = make_float2(av.w, av.w);
            *(float4*)&Bs[nb][bkk    ][bn4] = bv0;
            *(float4*)&Bs[nb][bkk + 8][bn4] = bv1;
            __syncthreads();
        }
    }

    // unpack packed accumulators -> 4 rows x 8 gate-cols
    float ga[4][8];
    #pragma unroll
    for (int r = 0; r < 4; r++)
        #pragma unroll
        for (int c = 0; c < 4; c++){
            ga[r][2 * c]     = lo32(acc[r][c]);
            ga[r][2 * c + 1] = hi32(acc[r][c]);
        }

    float bb[8];
    #pragma unroll
    for (int c = 0; c < 8; c++) bb[c] = g_bias[bn0 + tx * 8 + c];

    const bool last  = (t == TLEN - 1);
    const int  ubase = (bn0 + tx * 8) >> 2;   // hidden-unit index of col quad 0
    #pragma unroll
    for (int r = 0; r < 4; r++){
        const int b = bm0 + ty * 4 + r;
        #pragma unroll
        for (int uu = 0; uu < 2; uu++){
            const int u    = ubase + uu;
            const int base = uu * 4;
            float gi = sigf (ga[r][base + 0] + bb[base + 0]);
            float gf = sigf (ga[r][base + 1] + bb[base + 1]);
            float gg = tanh_(ga[r][base + 2] + bb[base + 2]);
            float go = sigf (ga[r][base + 3] + bb[base + 3]);
            float cold = g_c[b * HSZ + u];
            float cn = gf * cold + gi * gg;
            float hn = go * tanh_(cn);
            g_c[b * HSZ + u]   = cn;
            hwrite[b * HSZ + u] = hn;
            if (last){
                out[b * HSZ + u]      = hn;   // hn: [1,B,H]
                out[BH + b * HSZ + u] = cn;   // cn: [1,B,H]
            }
        }
    }
}

extern "C" void kernel_launch(void* const* d_in, const int* in_sizes, int n_in,
                              void* d_out, int out_size){
    const float* x    = (const float*)d_in[0];
    const float* W_ih = (const float*)d_in[1];
    const float* W_hh = (const float*)d_in[2];
    const float* b_ih = (const float*)d_in[3];
    const float* b_hh = (const float*)d_in[4];
    float* out = (float*)d_out;

    prep_kernel<<<(KTOT * FH + 255) / 256, 256>>>(W_ih, W_hh, b_ih, b_hh);

    dim3 grid(FH / BN, BATCH / BM);   // (8, 16) = 128 blocks
    for (int t = 0; t < TLEN; t++)
        lstm_step_kernel<<<grid, NTHREADS>>>(x, t, out);
}

// round 15
// speedup vs baseline: 1.0003x; 1.0003x over previous
#include <cuda_runtime.h>

#define BATCH 1024
#define TLEN  336
#define ISZ   64
#define HSZ   256
#define FH    1024      // 4*H
#define KTOT  320       // H + I
#define BM    64
#define BN    128
#define KT    16
#define NKT   (KTOT/KT) // 20
#define NTHREADS 256
#define ASTRIDE 136     // 2*64 duplicated + 8 pad
#define BH (BATCH*HSZ)

// Scratch in __device__ globals (no allocation allowed)
__device__ float g_Wcat[KTOT*FH];   // [k][n], n = 4*u + gate (i,f,g,o)
__device__ float g_bias[FH];        // b_ih + b_hh, reordered
__device__ float g_h[2][BH];        // double-buffered hidden state
__device__ float g_c[BH];           // cell state (tile-private per step)

typedef unsigned long long ull;

__device__ __forceinline__ void fma2(ull &d, ull a, ull b){
    // packed fp32x2 FMA (Blackwell dual fp32 lanes)
    asm("fma.rn.f32x2 %0, %1, %2, %0;" : "+l"(d) : "l"(a), "l"(b));
}
__device__ __forceinline__ float lo32(ull v){ return __uint_as_float((unsigned)v); }
__device__ __forceinline__ float hi32(ull v){ return __uint_as_float((unsigned)(v >> 32)); }

__device__ __forceinline__ float sigf(float x){ return 1.f / (1.f + __expf(-x)); }
// tanh(x) = 1 - 2/(1+exp(2x)); saturates cleanly at +/-1, no inf/inf NaN
__device__ __forceinline__ float tanh_(float x){ return 1.f - 2.f / (1.f + __expf(2.f * x)); }

// Build Wcat/bias, zero h0/c0. Runs once per kernel_launch (deterministic).
__global__ void prep_kernel(const float* __restrict__ W_ih, const float* __restrict__ W_hh,
                            const float* __restrict__ b_ih, const float* __restrict__ b_hh){
    int idx = blockIdx.x * blockDim.x + threadIdx.x;
    if (idx < KTOT * FH){
        int k = idx >> 10;          // 0..319
        int n = idx & (FH - 1);     // 0..1023
        int u = n >> 2, g = n & 3;  // gate order i,f,g,o
        g_Wcat[idx] = (k < HSZ) ? W_hh[(g * HSZ + u) * HSZ + k]
                                : W_ih[(g * HSZ + u) * ISZ + (k - HSZ)];
    }
    if (idx < FH){
        int u = idx >> 2, g = idx & 3;
        g_bias[idx] = b_ih[g * HSZ + u] + b_hh[g * HSZ + u];
    }
    if (idx < BH){
        g_c[idx]    = 0.f;
        g_h[0][idx] = 0.f;
    }
}

// One LSTM timestep: gates = [h | x_t] @ Wcat + bias, fused gate epilogue.
// Tile 64(M=batch) x 128(N=gate cols) per block; 256 threads, 4x8 micro-tile
// computed as 4x4 packed f32x2 accumulators.
__global__ void __launch_bounds__(NTHREADS, 1)
lstm_step_kernel(const float* __restrict__ x, int t, float* __restrict__ out){
    __shared__ float As2[2][KT][ASTRIDE];   // A duplicated: As2[k][2m]=As2[k][2m+1]=A[m][k]
    __shared__ float Bs [2][KT][BN];        // Bs[k][n]

    const float* __restrict__ hread  = g_h[t & 1];
    float*       __restrict__ hwrite = g_h[(t + 1) & 1];

    const int tid = threadIdx.x;
    const int bm0 = blockIdx.y * BM;
    const int bn0 = blockIdx.x * BN;
    const int ty  = tid >> 4,  tx  = tid & 15;    // 16x16 compute threads
    const int am  = tid >> 2,  akq = tid & 3;     // A loader: row, k-quad
    const int bn4 = (tid & 31) * 4, bkk = tid >> 5; // B loader

    ull acc[4][4];
    #pragma unroll
    for (int r = 0; r < 4; r++)
        #pragma unroll
        for (int c = 0; c < 4; c++) acc[r][c] = 0ULL;

    float4 av, bv0, bv1;
    // prefetch k-tile 0 (h source)
    av  = *(const float4*)&hread[(bm0 + am) * HSZ + akq * 4];
    bv0 = *(const float4*)&g_Wcat[(bkk    ) * FH + bn0 + bn4];
    bv1 = *(const float4*)&g_Wcat[(bkk + 8) * FH + bn0 + bn4];
    *(float2*)&As2[0][akq * 4 + 0][2 * am] = make_float2(av.x, av.x);
    *(float2*)&As2[0][akq * 4 + 1][2 * am] = make_float2(av.y, av.y);
    *(float2*)&As2[0][akq * 4 + 2][2 * am] = make_float2(av.z, av.z);
    *(float2*)&As2[0][akq * 4 + 3][2 * am] = make_float2(av.w, av.w);
    *(float4*)&Bs[0][bkk    ][bn4] = bv0;
    *(float4*)&Bs[0][bkk + 8][bn4] = bv1;
    __syncthreads();

    #pragma unroll 2
    for (int kt = 0; kt < NKT; kt++){
        const int cur = kt & 1;
        if (kt < NKT - 1){
            const int kn = kt + 1;
            if (kn < 16)   // h portion of K (k < 256)
                av = *(const float4*)&hread[(bm0 + am) * HSZ + kn * KT + akq * 4];
            else           // x portion of K (k >= 256)
                av = *(const float4*)&x[(size_t)(bm0 + am) * (TLEN * ISZ)
                                        + (size_t)t * ISZ + (kn - 16) * KT + akq * 4];
            bv0 = *(const float4*)&g_Wcat[(kn * KT + bkk    ) * FH + bn0 + bn4];
            bv1 = *(const float4*)&g_Wcat[(kn * KT + bkk + 8) * FH + bn0 + bn4];
        }
        const float* Ap = &As2[cur][0][0];
        const float* Bp = &Bs [cur][0][0];
        #pragma unroll
        for (int k = 0; k < KT; k++){
            ulonglong2 a01 = *(const ulonglong2*)(Ap + k * ASTRIDE + ty * 8);
            ulonglong2 a23 = *(const ulonglong2*)(Ap + k * ASTRIDE + ty * 8 + 4);
            ulonglong2 b01 = *(const ulonglong2*)(Bp + k * BN + tx * 8);
            ulonglong2 b23 = *(const ulonglong2*)(Bp + k * BN + tx * 8 + 4);
            ull ar[4] = {a01.x, a01.y, a23.x, a23.y};
            ull bc[4] = {b01.x, b01.y, b23.x, b23.y};
            #pragma unroll
            for (int r = 0; r < 4; r++)
                #pragma unroll
                for (int c = 0; c < 4; c++)
                    fma2(acc[r][c], ar[r], bc[c]);
        }
        if (kt < NKT - 1){
            const int nb = cur ^ 1;   // safe: nb was last read before previous sync
            *(float2*)&As2[nb][akq * 4 + 0][2 * am] = make_float2(av.x, av.x);
            *(float2*)&As2[nb][akq * 4 + 1][2 * am] = make_float2(av.y, av.y);
            *(float2*)&As2[nb][akq * 4 + 2][2 * am] = make_float2(av.z, av.z);
            *(float2*)&As2[nb][akq * 4 + 3][2 * am] = make_float2(av.w, av.w);
            *(float4*)&Bs[nb][bkk    ][bn4] = bv0;
            *(float4*)&Bs[nb][bkk + 8][bn4] = bv1;
            __syncthreads();
        }
    }

    // unpack packed accumulators -> 4 rows x 8 gate-cols
    float ga[4][8];
    #pragma unroll
    for (int r = 0; r < 4; r++)
        #pragma unroll
        for (int c = 0; c < 4; c++){
            ga[r][2 * c]     = lo32(acc[r][c]);
            ga[r][2 * c + 1] = hi32(acc[r][c]);
        }

    float bb[8];
    #pragma unroll
    for (int c = 0; c < 8; c++) bb[c] = g_bias[bn0 + tx * 8 + c];

    const bool last  = (t == TLEN - 1);
    const int  ubase = (bn0 + tx * 8) >> 2;   // hidden-unit index of col quad 0
    #pragma unroll
    for (int r = 0; r < 4; r++){
        const int b = bm0 + ty * 4 + r;
        #pragma unroll
        for (int uu = 0; uu < 2; uu++){
            const int u    = ubase + uu;
            const int base = uu * 4;
            float gi = sigf (ga[r][base + 0] + bb[base + 0]);
            float gf = sigf (ga[r][base + 1] + bb[base + 1]);
            float gg = tanh_(ga[r][base + 2] + bb[base + 2]);
            float go = sigf (ga[r][base + 3] + bb[base + 3]);
            float cold = g_c[b * HSZ + u];
            float cn = gf * cold + gi * gg;
            float hn = go * tanh_(cn);
            g_c[b * HSZ + u]   = cn;
            hwrite[b * HSZ + u] = hn;
            if (last){
                out[b * HSZ + u]      = hn;   // hn: [1,B,H]
                out[BH + b * HSZ + u] = cn;   // cn: [1,B,H]
            }
        }
    }
}

extern "C" void kernel_launch(void* const* d_in, const int* in_sizes, int n_in,
                              void* d_out, int out_size){
    const float* x    = (const float*)d_in[0];
    const float* W_ih = (const float*)d_in[1];
    const float* W_hh = (const float*)d_in[2];
    const float* b_ih = (const float*)d_in[3];
    const float* b_hh = (const float*)d_in[4];
    float* out = (float*)d_out;

    prep_kernel<<<(KTOT * FH + 255) / 256, 256>>>(W_ih, W_hh, b_ih, b_hh);

    dim3 grid(FH / BN, BATCH / BM);   // (8, 16) = 128 blocks
    for (int t = 0; t < TLEN; t++)
        lstm_step_kernel<<<grid, NTHREADS>>>(x, t, out);
}

// round 16
// speedup vs baseline: 1.0011x; 1.0008x over previous
#include <cuda_runtime.h>

#define BATCH 1024
#define TLEN  336
#define ISZ   64
#define HSZ   256
#define FH    1024      // 4*H
#define KTOT  320       // H + I
#define BM    64
#define BN    128
#define KT    16
#define NKT   (KTOT/KT) // 20
#define NTHREADS 256
#define ASTRIDE 136     // 2*64 duplicated + 8 pad
#define BH (BATCH*HSZ)

// Scratch in __device__ globals (no allocation allowed)
__device__ float g_Wcat[KTOT*FH];   // [k][n], n = 4*u + gate (i,f,g,o)
__device__ float g_bias[FH];        // b_ih + b_hh, reordered
__device__ float g_h[2][BH];        // double-buffered hidden state
__device__ float g_c[BH];           // cell state (tile-private per step)

typedef unsigned long long ull;

__device__ __forceinline__ void fma2(ull &d, ull a, ull b){
    // packed fp32x2 FMA (Blackwell dual fp32 lanes)
    asm("fma.rn.f32x2 %0, %1, %2, %0;" : "+l"(d) : "l"(a), "l"(b));
}
__device__ __forceinline__ float lo32(ull v){ return __uint_as_float((unsigned)v); }
__device__ __forceinline__ float hi32(ull v){ return __uint_as_float((unsigned)(v >> 32)); }

__device__ __forceinline__ float sigf(float x){ return 1.f / (1.f + __expf(-x)); }
// tanh(x) = 1 - 2/(1+exp(2x)); saturates cleanly at +/-1, no inf/inf NaN
__device__ __forceinline__ float tanh_(float x){ return 1.f - 2.f / (1.f + __expf(2.f * x)); }

// Build Wcat/bias, zero h0/c0. Runs once per kernel_launch (deterministic).
__global__ void prep_kernel(const float* __restrict__ W_ih, const float* __restrict__ W_hh,
                            const float* __restrict__ b_ih, const float* __restrict__ b_hh){
    int idx = blockIdx.x * blockDim.x + threadIdx.x;
    if (idx < KTOT * FH){
        int k = idx >> 10;          // 0..319
        int n = idx & (FH - 1);     // 0..1023
        int u = n >> 2, g = n & 3;  // gate order i,f,g,o
        g_Wcat[idx] = (k < HSZ) ? W_hh[(g * HSZ + u) * HSZ + k]
                                : W_ih[(g * HSZ + u) * ISZ + (k - HSZ)];
    }
    if (idx < FH){
        int u = idx >> 2, g = idx & 3;
        g_bias[idx] = b_ih[g * HSZ + u] + b_hh[g * HSZ + u];
    }
    if (idx < BH){
        g_c[idx]    = 0.f;
        g_h[0][idx] = 0.f;
    }
}

// One LSTM timestep: gates = [h | x_t] @ Wcat + bias, fused gate epilogue.
// Tile 64(M=batch) x 128(N=gate cols) per block; 256 threads, 4x8 micro-tile
// computed as 4x4 packed f32x2 accumulators.
__global__ void __launch_bounds__(NTHREADS, 1)
lstm_step_kernel(const float* __restrict__ x, int t, float* __restrict__ out){
    __shared__ float As2[2][KT][ASTRIDE];   // A duplicated: As2[k][2m]=As2[k][2m+1]=A[m][k]
    __shared__ float Bs [2][KT][BN];        // Bs[k][n]

    const float* __restrict__ hread  = g_h[t & 1];
    float*       __restrict__ hwrite = g_h[(t + 1) & 1];

    const int tid = threadIdx.x;
    const int bm0 = blockIdx.y * BM;
    const int bn0 = blockIdx.x * BN;
    const int ty  = tid >> 4,  tx  = tid & 15;    // 16x16 compute threads
    const int am  = tid >> 2,  akq = tid & 3;     // A loader: row, k-quad
    const int bn4 = (tid & 31) * 4, bkk = tid >> 5; // B loader

    ull acc[4][4];
    #pragma unroll
    for (int r = 0; r < 4; r++)
        #pragma unroll
        for (int c = 0; c < 4; c++) acc[r][c] = 0ULL;

    float4 av, bv0, bv1;
    // prefetch k-tile 0 (h source)
    av  = *(const float4*)&hread[(bm0 + am) * HSZ + akq * 4];
    bv0 = *(const float4*)&g_Wcat[(bkk    ) * FH + bn0 + bn4];
    bv1 = *(const float4*)&g_Wcat[(bkk + 8) * FH + bn0 + bn4];
    *(float2*)&As2[0][akq * 4 + 0][2 * am] = make_float2(av.x, av.x);
    *(float2*)&As2[0][akq * 4 + 1][2 * am] = make_float2(av.y, av.y);
    *(float2*)&As2[0][akq * 4 + 2][2 * am] = make_float2(av.z, av.z);
    *(float2*)&As2[0][akq * 4 + 3][2 * am] = make_float2(av.w, av.w);
    *(float4*)&Bs[0][bkk    ][bn4] = bv0;
    *(float4*)&Bs[0][bkk + 8][bn4] = bv1;
    __syncthreads();

    #pragma unroll 2
    for (int kt = 0; kt < NKT; kt++){
        const int cur = kt & 1;
        if (kt < NKT - 1){
            const int kn = kt + 1;
            if (kn < 16)   // h portion of K (k < 256)
                av = *(const float4*)&hread[(bm0 + am) * HSZ + kn * KT + akq * 4];
            else           // x portion of K (k >= 256)
                av = *(const float4*)&x[(size_t)(bm0 + am) * (TLEN * ISZ)
                                        + (size_t)t * ISZ + (kn - 16) * KT + akq * 4];
            bv0 = *(const float4*)&g_Wcat[(kn * KT + bkk    ) * FH + bn0 + bn4];
            bv1 = *(const float4*)&g_Wcat[(kn * KT + bkk + 8) * FH + bn0 + bn4];
        }
        const float* Ap = &As2[cur][0][0];
        const float* Bp = &Bs [cur][0][0];
        #pragma unroll
        for (int k = 0; k < KT; k++){
            ulonglong2 a01 = *(const ulonglong2*)(Ap + k * ASTRIDE + ty * 8);
            ulonglong2 a23 = *(const ulonglong2*)(Ap + k * ASTRIDE + ty * 8 + 4);
            ulonglong2 b01 = *(const ulonglong2*)(Bp + k * BN + tx * 8);
            ulonglong2 b23 = *(const ulonglong2*)(Bp + k * BN + tx * 8 + 4);
            ull ar[4] = {a01.x, a01.y, a23.x, a23.y};
            ull bc[4] = {b01.x, b01.y, b23.x, b23.y};
            #pragma unroll
            for (int r = 0; r < 4; r++)
                #pragma unroll
                for (int c = 0; c < 4; c++)
                    fma2(acc[r][c], ar[r], bc[c]);
        }
        if (kt < NKT - 1){
            const int nb = cur ^ 1;   // safe: nb was last read before previous sync
            *(float2*)&As2[nb][akq * 4 + 0][2 * am] = make_float2(av.x, av.x);
            *(float2*)&As2[nb][akq * 4 + 1][2 * am] = make_float2(av.y, av.y);
            *(float2*)&As2[nb][akq * 4 + 2][2 * am] = make_float2(av.z, av.z);
            *(float2*)&As2[nb][akq * 4 + 3][2 * am] = make_float2(av.w, av.w);
            *(float4*)&Bs[nb][bkk    ][bn4] = bv0;
            *(float4*)&Bs[nb][bkk + 8][bn4] = bv1;
            __syncthreads();
        }
    }

    // unpack packed accumulators -> 4 rows x 8 gate-cols
    float ga[4][8];
    #pragma unroll
    for (int r = 0; r < 4; r++)
        #pragma unroll
        for (int c = 0; c < 4; c++){
            ga[r][2 * c]     = lo32(acc[r][c]);
            ga[r][2 * c + 1] = hi32(acc[r][c]);
        }

    float bb[8];
    #pragma unroll
    for (int c = 0; c < 8; c++) bb[c] = g_bias[bn0 + tx * 8 + c];

    const bool last  = (t == TLEN - 1);
    const int  ubase = (bn0 + tx * 8) >> 2;   // hidden-unit index of col quad 0
    #pragma unroll
    for (int r = 0; r < 4; r++){
        const int b = bm0 + ty * 4 + r;
        #pragma unroll
        for (int uu = 0; uu < 2; uu++){
            const int u    = ubase + uu;
            const int base = uu * 4;
            float gi = sigf (ga[r][base + 0] + bb[base + 0]);
            float gf = sigf (ga[r][base + 1] + bb[base + 1]);
            float gg = tanh_(ga[r][base + 2] + bb[base + 2]);
            float go = sigf (ga[r][base + 3] + bb[base + 3]);
            float cold = g_c[b * HSZ + u];
            float cn = gf * cold + gi * gg;
            float hn = go * tanh_(cn);
            g_c[b * HSZ + u]   = cn;
            hwrite[b * HSZ + u] = hn;
            if (last){
                out[b * HSZ + u]      = hn;   // hn: [1,B,H]
                out[BH + b * HSZ + u] = cn;   // cn: [1,B,H]
            }
        }
    }
}

extern "C" void kernel_launch(void* const* d_in, const int* in_sizes, int n_in,
                              void* d_out, int out_size){
    const float* x    = (const float*)d_in[0];
    const float* W_ih = (const float*)d_in[1];
    const float* W_hh = (const float*)d_in[2];
    const float* b_ih = (const float*)d_in[3];
    const float* b_hh = (const float*)d_in[4];
    float* out = (float*)d_out;

    prep_kernel<<<(KTOT * FH + 255) / 256, 256>>>(W_ih, W_hh, b_ih, b_hh);

    dim3 grid(FH / BN, BATCH / BM);   // (8, 16) = 128 blocks
    for (int t = 0; t < TLEN; t++)
        lstm_step_kernel<<<grid, NTHREADS>>>(x, t, out);
}